// round 7
// baseline (speedup 1.0000x reference)
#include <cuda_runtime.h>
#include <cuda_bf16.h>
#include <cuda_fp16.h>
#include <cstdint>
#include <math.h>

#define BB 4
#define LL 8192
#define DD 256
#define NLEV 13
#define NOUT 512

// ---------------- scratch (static device globals; no allocation) ----------------
__device__ float g_xt[BB * DD * LL];        // rmsnorm'd x, (b,d,t) layout
__device__ float g_yt[BB * DD * LL];        // gelu output, (b,d,t) layout
__device__ uint32_t g_whp[NOUT * (DD / 2)]; // W^T reordered into GLU pairs, fp16 k-pair packed
__device__ float g_br[NOUT];                // reordered bias

// ---------------- kernel 0: weight prep (fp16 + transpose + pair-reorder) -------
__global__ void prep_kernel(const float* __restrict__ cw, const float* __restrict__ cb) {
    int idx = blockIdx.x * 256 + threadIdx.x;
    int n = idx >> 7;
    int kp = idx & 127;
    int k0 = kp * 2;
    int oc = (n & 1) ? (DD + (n >> 1)) : (n >> 1);
    float v0 = cw[k0 * NOUT + oc];
    float v1 = cw[(k0 + 1) * NOUT + oc];
    __half2 h = __floats2half2_rn(v0, v1);
    g_whp[n * 128 + kp] = *(uint32_t*)&h;
    if (idx < NOUT) {
        int occ = (idx & 1) ? (DD + (idx >> 1)) : (idx >> 1);
        g_br[idx] = cb[occ];
    }
}

// ---------------- kernel 1: rmsnorm + transpose to (b,d,t) ----------------------
__global__ void rmsnorm_kernel(const float* __restrict__ x, const float* __restrict__ rs) {
    __shared__ float tile[32][257];
    int b = blockIdx.x >> 8;
    int t0 = (blockIdx.x & 255) * 32;
    int w = threadIdx.x >> 5, lane = threadIdx.x & 31;
    #pragma unroll
    for (int rr = 0; rr < 4; rr++) {
        int tr = w * 4 + rr;
        size_t base = ((size_t)(b * LL + t0 + tr)) * DD;
        float v[8]; float ss = 0.f;
        #pragma unroll
        for (int k = 0; k < 8; k++) { v[k] = x[base + lane + 32 * k]; ss += v[k] * v[k]; }
        #pragma unroll
        for (int o = 16; o > 0; o >>= 1) ss += __shfl_xor_sync(0xffffffffu, ss, o);
        float inv = rsqrtf(ss * (1.f / DD) + 1e-6f);
        #pragma unroll
        for (int k = 0; k < 8; k++) tile[tr][lane + 32 * k] = v[k] * inv * rs[lane + 32 * k];
    }
    __syncthreads();
    #pragma unroll 8
    for (int dd = 0; dd < 32; dd++) {
        int d = w * 32 + dd;
        g_xt[((size_t)(b * DD + d)) * LL + t0 + lane] = tile[lane][d];
    }
}

// ---------------- kernel 2: 13-level dilated depthwise cascade + gelu -----------
__device__ __forceinline__ float gelu_f(float v) {
    float u = 0.7978845608028654f * (v + 0.044715f * v * v * v);
    return 0.5f * v * (1.f + tanhf(u));
}

__global__ void __launch_bounds__(256)
cascade_kernel(const float* __restrict__ h0,
               const float* __restrict__ h1,
               const float* __restrict__ wv) {
    extern __shared__ float sb[];
    float* srcb = sb;
    float* dstb = sb + LL;
    int b = blockIdx.x >> 8, d = blockIdx.x & 255;
    float h00 = h0[d * 2], h01 = h0[d * 2 + 1];
    float h10 = h1[d * 2], h11 = h1[d * 2 + 1];
    float w0 = wv[d];
    float wlast = wv[(NLEV + 1) * DD + d];
    size_t base = ((size_t)(b * DD + d)) * LL;
    int tid = threadIdx.x;
    float a[32], y[32];
    #pragma unroll
    for (int k = 0; k < 32; k++) {
        int t = tid + 256 * k;
        a[k] = g_xt[base + t];
        srcb[t] = a[k];
        y[k] = w0 * a[k];
    }
    for (int j = 0; j < 8; j++) {
        int dil = 1 << j;
        float wj = wv[(j + 1) * DD + d];
        __syncthreads();
        #pragma unroll
        for (int k = 0; k < 32; k++) {
            int t = tid + 256 * k;
            float prev = (t >= dil) ? srcb[t - dil] : 0.f;
            y[k] += wj * (h10 * prev + h11 * a[k]);
            a[k] = h00 * prev + h01 * a[k];
            if (j != 7) dstb[t] = a[k];
        }
        float* tmp = srcb; srcb = dstb; dstb = tmp;
    }
    #pragma unroll
    for (int j = 8; j < NLEV; j++) {
        int c = 1 << (j - 8);
        float wj = wv[(j + 1) * DD + d];
        #pragma unroll
        for (int k = 31; k >= 0; k--) {
            float prev = (k >= c) ? a[k - c] : 0.f;
            y[k] += wj * (h10 * prev + h11 * a[k]);
            a[k] = h00 * prev + h01 * a[k];
        }
    }
    #pragma unroll
    for (int k = 0; k < 32; k++) {
        int t = tid + 256 * k;
        g_yt[base + t] = gelu_f(y[k] + wlast * a[k]);
    }
}

// ---------------- kernel 3: pipelined ldmatrix GEMM + GLU + residual ------------
__device__ __forceinline__ void mma16816(float* c, const uint32_t* a, const uint32_t* b) {
    asm volatile(
        "mma.sync.aligned.m16n8k16.row.col.f32.f16.f16.f32 "
        "{%0,%1,%2,%3}, {%4,%5,%6,%7}, {%8,%9}, {%0,%1,%2,%3};\n"
        : "+f"(c[0]), "+f"(c[1]), "+f"(c[2]), "+f"(c[3])
        : "r"(a[0]), "r"(a[1]), "r"(a[2]), "r"(a[3]), "r"(b[0]), "r"(b[1]));
}
__device__ __forceinline__ void ldsm4(uint32_t* r, uint32_t addr) {
    asm volatile("ldmatrix.sync.aligned.m8n8.x4.shared.b16 {%0,%1,%2,%3}, [%4];"
                 : "=r"(r[0]), "=r"(r[1]), "=r"(r[2]), "=r"(r[3]) : "r"(addr));
}
__device__ __forceinline__ uint32_t smem_u32(const void* p) {
    uint32_t a;
    asm("{ .reg .u64 t; cvta.to.shared.u64 t, %1; cvt.u32.u64 %0, t; }" : "=r"(a) : "l"(p));
    return a;
}
__device__ __forceinline__ void cpasync16(uint32_t dst, const void* src) {
    asm volatile("cp.async.cg.shared.global [%0], [%1], 16;" :: "r"(dst), "l"(src));
}

// smem layout (bytes):
//   B:      [n=128][pitch 132 words]           = 67584
//   A bufs: 2 x { hi plane, lo plane } each [m=128][pitch 20 words] = 2*2*10240 = 40960
#define B_BYTES   67584
#define APLANE    10240
#define ABUF      20480
#define GEMM_SMEM (B_BYTES + 2 * ABUF)

__global__ void __launch_bounds__(512)
gemm_glu_mma_kernel(const float* __restrict__ xin, float* __restrict__ out) {
    extern __shared__ char smem[];
    uint32_t sbase = smem_u32(smem);
    uint32_t b_smem = sbase;
    uint32_t a_smem = sbase + B_BYTES;

    int bid = blockIdx.x;               // 1024 = 256 m-tiles x 4 n-tiles (n inner for L2 reuse of A)
    int m0 = (bid >> 2) * 128;          // flat row (b*L + t)
    int n0 = (bid & 3) * 128;           // reordered column base
    int b = m0 >> 13;
    int t0 = m0 & 8191;

    int tid = threadIdx.x;
    int warp = tid >> 5, lane = tid & 31;
    int m0w = (warp >> 2) * 32, n0w = (warp & 3) * 32;
    int g = lane >> 2, tg = lane & 3;

    int tloc = tid & 127;               // A-loader row (t)
    int q = tid >> 7;                   // A-loader k-quarter (0..3)

    // ---- prologue: B whole-K preload via cp.async ----
    {
        int r = tid >> 2, seg = tid & 3;
        const uint4* src = (const uint4*)(g_whp + (size_t)(n0 + r) * 128 + seg * 32);
        uint32_t dst = b_smem + (uint32_t)(r * 132 + seg * 32) * 4;
        #pragma unroll
        for (int u = 0; u < 8; u++) cpasync16(dst + u * 16, src + u);
        asm volatile("cp.async.commit_group;" ::: "memory");
    }

    // ---- prologue: A chunk 0 -> buf 0 ----
    const float* Ag = g_yt + (size_t)(b * DD) * LL + t0 + tloc;  // + d*LL
    {
        float f[8];
        #pragma unroll
        for (int i = 0; i < 4; i++) {
            int d = (q * 4 + i) * 2;
            f[i * 2]     = Ag[(size_t)d * LL];
            f[i * 2 + 1] = Ag[(size_t)(d + 1) * LL];
        }
        uint4 hw, lw;
        uint32_t* hp = (uint32_t*)&hw; uint32_t* lp = (uint32_t*)&lw;
        #pragma unroll
        for (int i = 0; i < 4; i++) {
            __half h0v = __float2half_rn(f[i * 2]);
            __half h1v = __float2half_rn(f[i * 2 + 1]);
            __half l0v = __float2half_rn(f[i * 2] - __half2float(h0v));
            __half l1v = __float2half_rn(f[i * 2 + 1] - __half2float(h1v));
            __half2 ph = __halves2half2(h0v, h1v);
            __half2 pl = __halves2half2(l0v, l1v);
            hp[i] = *(uint32_t*)&ph; lp[i] = *(uint32_t*)&pl;
        }
        uint32_t doff = (uint32_t)(tloc * 20 + q * 4) * 4;
        *(uint4*)(smem + B_BYTES + doff) = hw;
        *(uint4*)(smem + B_BYTES + APLANE + doff) = lw;
    }
    asm volatile("cp.async.wait_group 0;" ::: "memory");
    __syncthreads();

    // ldmatrix per-thread base offsets
    uint32_t aoff[2], boff[2];
    #pragma unroll
    for (int mi = 0; mi < 2; mi++)
        aoff[mi] = (uint32_t)((m0w + mi * 16 + (lane & 15)) * 20 + (lane >> 4) * 4) * 4;
    #pragma unroll
    for (int nj = 0; nj < 2; nj++)
        boff[nj] = b_smem + (uint32_t)((n0w + nj * 16 + ((lane >> 4) << 3) + (lane & 7)) * 132
                                       + ((lane >> 3) & 1) * 4) * 4;

    float acc[2][4][4];
    #pragma unroll
    for (int i = 0; i < 2; i++)
        #pragma unroll
        for (int j = 0; j < 4; j++)
            #pragma unroll
            for (int p = 0; p < 4; p++) acc[i][j][p] = 0.f;

    for (int kc = 0; kc < 8; kc++) {
        float f[8];
        if (kc < 7) {
            #pragma unroll
            for (int i = 0; i < 4; i++) {
                int d = (kc + 1) * 32 + (q * 4 + i) * 2;
                f[i * 2]     = Ag[(size_t)d * LL];
                f[i * 2 + 1] = Ag[(size_t)(d + 1) * LL];
            }
        }
        uint32_t abase = a_smem + (uint32_t)(kc & 1) * ABUF;
        #pragma unroll
        for (int ks = 0; ks < 2; ks++) {
            uint32_t ah[2][4], al[2][4], bf[2][4];
            ldsm4(ah[0], abase + aoff[0] + ks * 32);
            ldsm4(ah[1], abase + aoff[1] + ks * 32);
            ldsm4(al[0], abase + APLANE + aoff[0] + ks * 32);
            ldsm4(al[1], abase + APLANE + aoff[1] + ks * 32);
            ldsm4(bf[0], boff[0] + (uint32_t)(kc * 16 + ks * 8) * 4);
            ldsm4(bf[1], boff[1] + (uint32_t)(kc * 16 + ks * 8) * 4);
            #pragma unroll
            for (int mi = 0; mi < 2; mi++)
                #pragma unroll
                for (int nj = 0; nj < 2; nj++) {
                    mma16816(acc[mi][nj * 2 + 0], ah[mi], &bf[nj][0]);
                    mma16816(acc[mi][nj * 2 + 1], ah[mi], &bf[nj][2]);
                    mma16816(acc[mi][nj * 2 + 0], al[mi], &bf[nj][0]);
                    mma16816(acc[mi][nj * 2 + 1], al[mi], &bf[nj][2]);
                }
        }
        if (kc < 7) {
            uint4 hw, lw;
            uint32_t* hp = (uint32_t*)&hw; uint32_t* lp = (uint32_t*)&lw;
            #pragma unroll
            for (int i = 0; i < 4; i++) {
                __half h0v = __float2half_rn(f[i * 2]);
                __half h1v = __float2half_rn(f[i * 2 + 1]);
                __half l0v = __float2half_rn(f[i * 2] - __half2float(h0v));
                __half l1v = __float2half_rn(f[i * 2 + 1] - __half2float(h1v));
                __half2 ph = __halves2half2(h0v, h1v);
                __half2 pl = __halves2half2(l0v, l1v);
                hp[i] = *(uint32_t*)&ph; lp[i] = *(uint32_t*)&lp[0];
                lp[i] = *(uint32_t*)&pl;
            }
            uint32_t doff = (uint32_t)(((kc + 1) & 1) * ABUF) + (uint32_t)(tloc * 20 + q * 4) * 4;
            *(uint4*)(smem + B_BYTES + doff) = hw;
            *(uint4*)(smem + B_BYTES + APLANE + doff) = lw;
        }
        __syncthreads();
    }

    // ---- epilogue: bias + GLU (paired cols) + residual, direct stores ----
    #pragma unroll
    for (int mi = 0; mi < 2; mi++) {
        int r0 = m0 + m0w + mi * 16 + g;
        #pragma unroll
        for (int ni = 0; ni < 4; ni++) {
            int np = n0 + n0w + ni * 8 + tg * 2;
            float bb0 = g_br[np], bb1 = g_br[np + 1];
            int oc = np >> 1;
            float s0 = acc[mi][ni][0] + bb0;
            float s1 = acc[mi][ni][1] + bb1;
            float s2 = acc[mi][ni][2] + bb0;
            float s3 = acc[mi][ni][3] + bb1;
            size_t o0 = (size_t)r0 * DD + oc;
            size_t o1 = (size_t)(r0 + 8) * DD + oc;
            out[o0] = s0 * (1.f / (1.f + __expf(-s1))) + xin[o0];
            out[o1] = s2 * (1.f / (1.f + __expf(-s3))) + xin[o1];
        }
    }
}

// ---------------- launch ---------------------------------------------------------
extern "C" void kernel_launch(void* const* d_in, const int* in_sizes, int n_in,
                              void* d_out, int out_size) {
    const float* x  = (const float*)d_in[0];  // (B, L, D)
    const float* rs = (const float*)d_in[1];  // (D,)
    const float* h0 = (const float*)d_in[2];  // (D, 2)
    const float* h1 = (const float*)d_in[3];  // (D, 2)
    const float* wv = (const float*)d_in[4];  // (15, D)
    const float* cw = (const float*)d_in[5];  // (D, 2D)
    const float* cb = (const float*)d_in[6];  // (2D,)
    float* out = (float*)d_out;

    cudaFuncSetAttribute(cascade_kernel, cudaFuncAttributeMaxDynamicSharedMemorySize, 2 * LL * 4);
    cudaFuncSetAttribute(gemm_glu_mma_kernel, cudaFuncAttributeMaxDynamicSharedMemorySize, GEMM_SMEM);

    prep_kernel<<<256, 256>>>(cw, cb);
    rmsnorm_kernel<<<BB * (LL / 32), 256>>>(x, rs);
    cascade_kernel<<<BB * DD, 256, 2 * LL * 4>>>(h0, h1, wv);
    gemm_glu_mma_kernel<<<BB * (LL / 128) * 4, 512, GEMM_SMEM>>>(x, out);
}

// round 8
// speedup vs baseline: 1.3031x; 1.3031x over previous
#include <cuda_runtime.h>
#include <cuda_bf16.h>
#include <cuda_fp16.h>
#include <cstdint>
#include <math.h>

#define BB 4
#define LL 8192
#define DD 256
#define NLEV 13
#define NOUT 512

// ---------------- scratch (static device globals; no allocation) ----------------
__device__ float g_xt[BB * DD * LL];        // rmsnorm'd x, (b,d,t) layout
__device__ float g_yt[BB * DD * LL];        // gelu output, (b,d,t) layout
__device__ uint32_t g_whp[NOUT * (DD / 2)]; // W^T reordered into GLU pairs, fp16 k-pair packed
__device__ float g_br[NOUT];                // reordered bias

// ---------------- kernel 0: weight prep (fp16 + transpose + pair-reorder) -------
__global__ void prep_kernel(const float* __restrict__ cw, const float* __restrict__ cb) {
    int idx = blockIdx.x * 256 + threadIdx.x;
    int n = idx >> 7;
    int kp = idx & 127;
    int k0 = kp * 2;
    int oc = (n & 1) ? (DD + (n >> 1)) : (n >> 1);
    float v0 = cw[k0 * NOUT + oc];
    float v1 = cw[(k0 + 1) * NOUT + oc];
    __half2 h = __floats2half2_rn(v0, v1);
    g_whp[n * 128 + kp] = *(uint32_t*)&h;
    if (idx < NOUT) {
        int occ = (idx & 1) ? (DD + (idx >> 1)) : (idx >> 1);
        g_br[idx] = cb[occ];
    }
}

// ---------------- kernel 1: rmsnorm + transpose to (b,d,t) ----------------------
__global__ void rmsnorm_kernel(const float* __restrict__ x, const float* __restrict__ rs) {
    __shared__ float tile[32][257];
    int b = blockIdx.x >> 8;
    int t0 = (blockIdx.x & 255) * 32;
    int w = threadIdx.x >> 5, lane = threadIdx.x & 31;
    #pragma unroll
    for (int rr = 0; rr < 4; rr++) {
        int tr = w * 4 + rr;
        size_t base = ((size_t)(b * LL + t0 + tr)) * DD;
        float v[8]; float ss = 0.f;
        #pragma unroll
        for (int k = 0; k < 8; k++) { v[k] = x[base + lane + 32 * k]; ss += v[k] * v[k]; }
        #pragma unroll
        for (int o = 16; o > 0; o >>= 1) ss += __shfl_xor_sync(0xffffffffu, ss, o);
        float inv = rsqrtf(ss * (1.f / DD) + 1e-6f);
        #pragma unroll
        for (int k = 0; k < 8; k++) tile[tr][lane + 32 * k] = v[k] * inv * rs[lane + 32 * k];
    }
    __syncthreads();
    #pragma unroll 8
    for (int dd = 0; dd < 32; dd++) {
        int d = w * 32 + dd;
        g_xt[((size_t)(b * DD + d)) * LL + t0 + lane] = tile[lane][d];
    }
}

// ---------------- kernel 2: 13-level dilated depthwise cascade + gelu -----------
__device__ __forceinline__ float gelu_f(float v) {
    float u = 0.7978845608028654f * (v + 0.044715f * v * v * v);
    return 0.5f * v * (1.f + tanhf(u));
}

__global__ void __launch_bounds__(256)
cascade_kernel(const float* __restrict__ h0,
               const float* __restrict__ h1,
               const float* __restrict__ wv) {
    extern __shared__ float sb[];
    float* srcb = sb;
    float* dstb = sb + LL;
    int b = blockIdx.x >> 8, d = blockIdx.x & 255;
    float h00 = h0[d * 2], h01 = h0[d * 2 + 1];
    float h10 = h1[d * 2], h11 = h1[d * 2 + 1];
    float w0 = wv[d];
    float wlast = wv[(NLEV + 1) * DD + d];
    size_t base = ((size_t)(b * DD + d)) * LL;
    int tid = threadIdx.x;
    float a[32], y[32];
    #pragma unroll
    for (int k = 0; k < 32; k++) {
        int t = tid + 256 * k;
        a[k] = g_xt[base + t];
        srcb[t] = a[k];
        y[k] = w0 * a[k];
    }
    for (int j = 0; j < 8; j++) {
        int dil = 1 << j;
        float wj = wv[(j + 1) * DD + d];
        __syncthreads();
        #pragma unroll
        for (int k = 0; k < 32; k++) {
            int t = tid + 256 * k;
            float prev = (t >= dil) ? srcb[t - dil] : 0.f;
            y[k] += wj * (h10 * prev + h11 * a[k]);
            a[k] = h00 * prev + h01 * a[k];
            if (j != 7) dstb[t] = a[k];
        }
        float* tmp = srcb; srcb = dstb; dstb = tmp;
    }
    #pragma unroll
    for (int j = 8; j < NLEV; j++) {
        int c = 1 << (j - 8);
        float wj = wv[(j + 1) * DD + d];
        #pragma unroll
        for (int k = 31; k >= 0; k--) {
            float prev = (k >= c) ? a[k - c] : 0.f;
            y[k] += wj * (h10 * prev + h11 * a[k]);
            a[k] = h00 * prev + h01 * a[k];
        }
    }
    #pragma unroll
    for (int k = 0; k < 32; k++) {
        int t = tid + 256 * k;
        g_yt[base + t] = gelu_f(y[k] + wlast * a[k]);
    }
}

// ---------------- kernel 3: pipelined ldmatrix GEMM + GLU + residual ------------
__device__ __forceinline__ void mma16816(float* c, const uint32_t* a, const uint32_t* b) {
    asm("mma.sync.aligned.m16n8k16.row.col.f32.f16.f16.f32 "
        "{%0,%1,%2,%3}, {%4,%5,%6,%7}, {%8,%9}, {%0,%1,%2,%3};\n"
        : "+f"(c[0]), "+f"(c[1]), "+f"(c[2]), "+f"(c[3])
        : "r"(a[0]), "r"(a[1]), "r"(a[2]), "r"(a[3]), "r"(b[0]), "r"(b[1]));
}
__device__ __forceinline__ void ldsm4(uint32_t* r, uint32_t addr) {
    asm volatile("ldmatrix.sync.aligned.m8n8.x4.shared.b16 {%0,%1,%2,%3}, [%4];"
                 : "=r"(r[0]), "=r"(r[1]), "=r"(r[2]), "=r"(r[3]) : "r"(addr));
}
__device__ __forceinline__ uint32_t smem_u32(const void* p) {
    uint32_t a;
    asm("{ .reg .u64 t; cvta.to.shared.u64 t, %1; cvt.u32.u64 %0, t; }" : "=r"(a) : "l"(p));
    return a;
}
__device__ __forceinline__ void cpasync16(uint32_t dst, const void* src) {
    asm volatile("cp.async.cg.shared.global [%0], [%1], 16;" :: "r"(dst), "l"(src));
}

// smem layout (bytes):
//   B:      [n=128][pitch 132 words]  = 67584
//   A bufs: 2 x [m=128][pitch 20 words] = 2*10240 = 20480   (single fp16 plane)
#define B_BYTES   67584
#define APLANE    10240
#define GEMM_SMEM (B_BYTES + 2 * APLANE)

__global__ void __launch_bounds__(512)
gemm_glu_mma_kernel(const float* __restrict__ xin, float* __restrict__ out) {
    extern __shared__ char smem[];
    uint32_t sbase = smem_u32(smem);
    uint32_t b_smem = sbase;
    uint32_t a_smem = sbase + B_BYTES;

    int bid = blockIdx.x;               // 1024 = 256 m-tiles x 4 n-tiles
    int m0 = (bid >> 2) * 128;          // flat row (b*L + t)
    int n0 = (bid & 3) * 128;           // reordered column base
    int b = m0 >> 13;
    int t0 = m0 & 8191;

    int tid = threadIdx.x;
    int warp = tid >> 5, lane = tid & 31;
    int m0w = (warp >> 2) * 32, n0w = (warp & 3) * 32;
    int g = lane >> 2, tg = lane & 3;

    int tloc = tid & 127;               // A-loader row (t)
    int q = tid >> 7;                   // A-loader k-quarter (0..3)

    // ---- prologue: B whole-K preload via cp.async ----
    {
        int r = tid >> 2, seg = tid & 3;
        const uint4* src = (const uint4*)(g_whp + (size_t)(n0 + r) * 128 + seg * 32);
        uint32_t dst = b_smem + (uint32_t)(r * 132 + seg * 32) * 4;
        #pragma unroll
        for (int u = 0; u < 8; u++) cpasync16(dst + u * 16, src + u);
        asm volatile("cp.async.commit_group;" ::: "memory");
    }

    // ---- prologue: A chunk 0 -> buf 0 (fp16 round-to-nearest, single plane) ----
    const float* Ag = g_yt + (size_t)(b * DD) * LL + t0 + tloc;  // + d*LL
    {
        uint4 hw;
        uint32_t* hp = (uint32_t*)&hw;
        #pragma unroll
        for (int i = 0; i < 4; i++) {
            int d = (q * 4 + i) * 2;
            __half2 ph = __floats2half2_rn(Ag[(size_t)d * LL], Ag[(size_t)(d + 1) * LL]);
            hp[i] = *(uint32_t*)&ph;
        }
        *(uint4*)(smem + B_BYTES + (uint32_t)(tloc * 20 + q * 4) * 4) = hw;
    }
    asm volatile("cp.async.wait_group 0;" ::: "memory");
    __syncthreads();

    // ldmatrix per-thread base offsets
    uint32_t aoff[2], boff[2];
    #pragma unroll
    for (int mi = 0; mi < 2; mi++)
        aoff[mi] = (uint32_t)((m0w + mi * 16 + (lane & 15)) * 20 + (lane >> 4) * 4) * 4;
    #pragma unroll
    for (int nj = 0; nj < 2; nj++)
        boff[nj] = b_smem + (uint32_t)((n0w + nj * 16 + ((lane >> 4) << 3) + (lane & 7)) * 132
                                       + ((lane >> 3) & 1) * 4) * 4;

    float acc[2][4][4];
    #pragma unroll
    for (int i = 0; i < 2; i++)
        #pragma unroll
        for (int j = 0; j < 4; j++)
            #pragma unroll
            for (int p = 0; p < 4; p++) acc[i][j][p] = 0.f;

    for (int kc = 0; kc < 8; kc++) {
        float f[8];
        if (kc < 7) {
            #pragma unroll
            for (int i = 0; i < 4; i++) {
                int d = (kc + 1) * 32 + (q * 4 + i) * 2;
                f[i * 2]     = Ag[(size_t)d * LL];
                f[i * 2 + 1] = Ag[(size_t)(d + 1) * LL];
            }
        }
        uint32_t abase = a_smem + (uint32_t)(kc & 1) * APLANE;
        #pragma unroll
        for (int ks = 0; ks < 2; ks++) {
            uint32_t ah[2][4], bf[2][4];
            ldsm4(ah[0], abase + aoff[0] + ks * 32);
            ldsm4(ah[1], abase + aoff[1] + ks * 32);
            ldsm4(bf[0], boff[0] + (uint32_t)(kc * 16 + ks * 8) * 4);
            ldsm4(bf[1], boff[1] + (uint32_t)(kc * 16 + ks * 8) * 4);
            // 8 mma, all distinct accumulators (reuse distance = 8)
            #pragma unroll
            for (int mi = 0; mi < 2; mi++)
                #pragma unroll
                for (int nj = 0; nj < 2; nj++) {
                    mma16816(acc[mi][nj * 2 + 0], ah[mi], &bf[nj][0]);
                    mma16816(acc[mi][nj * 2 + 1], ah[mi], &bf[nj][2]);
                }
        }
        if (kc < 7) {
            uint4 hw;
            uint32_t* hp = (uint32_t*)&hw;
            #pragma unroll
            for (int i = 0; i < 4; i++) {
                __half2 ph = __floats2half2_rn(f[i * 2], f[i * 2 + 1]);
                hp[i] = *(uint32_t*)&ph;
            }
            uint32_t doff = (uint32_t)(((kc + 1) & 1) * APLANE)
                          + (uint32_t)(tloc * 20 + q * 4) * 4;
            *(uint4*)(smem + B_BYTES + doff) = hw;
        }
        __syncthreads();
    }

    // ---- epilogue: bias + GLU (paired cols) + residual, direct stores ----
    #pragma unroll
    for (int mi = 0; mi < 2; mi++) {
        int r0 = m0 + m0w + mi * 16 + g;
        #pragma unroll
        for (int ni = 0; ni < 4; ni++) {
            int np = n0 + n0w + ni * 8 + tg * 2;
            float bb0 = g_br[np], bb1 = g_br[np + 1];
            int oc = np >> 1;
            float s0 = acc[mi][ni][0] + bb0;
            float s1 = acc[mi][ni][1] + bb1;
            float s2 = acc[mi][ni][2] + bb0;
            float s3 = acc[mi][ni][3] + bb1;
            size_t o0 = (size_t)r0 * DD + oc;
            size_t o1 = (size_t)(r0 + 8) * DD + oc;
            out[o0] = s0 * (1.f / (1.f + __expf(-s1))) + xin[o0];
            out[o1] = s2 * (1.f / (1.f + __expf(-s3))) + xin[o1];
        }
    }
}

// ---------------- launch ---------------------------------------------------------
extern "C" void kernel_launch(void* const* d_in, const int* in_sizes, int n_in,
                              void* d_out, int out_size) {
    const float* x  = (const float*)d_in[0];  // (B, L, D)
    const float* rs = (const float*)d_in[1];  // (D,)
    const float* h0 = (const float*)d_in[2];  // (D, 2)
    const float* h1 = (const float*)d_in[3];  // (D, 2)
    const float* wv = (const float*)d_in[4];  // (15, D)
    const float* cw = (const float*)d_in[5];  // (D, 2D)
    const float* cb = (const float*)d_in[6];  // (2D,)
    float* out = (float*)d_out;

    cudaFuncSetAttribute(cascade_kernel, cudaFuncAttributeMaxDynamicSharedMemorySize, 2 * LL * 4);
    cudaFuncSetAttribute(gemm_glu_mma_kernel, cudaFuncAttributeMaxDynamicSharedMemorySize, GEMM_SMEM);

    prep_kernel<<<256, 256>>>(cw, cb);
    rmsnorm_kernel<<<BB * (LL / 32), 256>>>(x, rs);
    cascade_kernel<<<BB * DD, 256, 2 * LL * 4>>>(h0, h1, wv);
    gemm_glu_mma_kernel<<<BB * (LL / 128) * 4, 512, GEMM_SMEM>>>(x, out);
}

// round 9
// speedup vs baseline: 1.3194x; 1.0125x over previous
#include <cuda_runtime.h>
#include <cuda_bf16.h>
#include <cuda_fp16.h>
#include <cstdint>
#include <math.h>

#define BB 4
#define LL 8192
#define DD 256
#define NLEV 13
#define NOUT 512

// ---------------- scratch (static device globals; no allocation) ----------------
__device__ float g_xt[BB * DD * LL];          // rmsnorm'd x, (b,d,t) layout
__device__ __half g_yth[BB * DD * LL];        // gelu output fp16, (b,d,t) layout
__device__ __half g_yh[(size_t)BB * LL * DD]; // gelu output fp16, row-major (b*L+t, d)
__device__ uint32_t g_whp[NOUT * (DD / 2)];   // W^T reordered into GLU pairs, fp16 k-pair packed
__device__ float g_br[NOUT];                  // reordered bias

// ---------------- kernel 0: weight prep (fp16 + transpose + pair-reorder) -------
__global__ void prep_kernel(const float* __restrict__ cw, const float* __restrict__ cb) {
    int idx = blockIdx.x * 256 + threadIdx.x;
    int n = idx >> 7;
    int kp = idx & 127;
    int k0 = kp * 2;
    int oc = (n & 1) ? (DD + (n >> 1)) : (n >> 1);
    float v0 = cw[k0 * NOUT + oc];
    float v1 = cw[(k0 + 1) * NOUT + oc];
    __half2 h = __floats2half2_rn(v0, v1);
    g_whp[n * 128 + kp] = *(uint32_t*)&h;
    if (idx < NOUT) {
        int occ = (idx & 1) ? (DD + (idx >> 1)) : (idx >> 1);
        g_br[idx] = cb[occ];
    }
}

// ---------------- kernel 1: rmsnorm + transpose to (b,d,t) ----------------------
__global__ void rmsnorm_kernel(const float* __restrict__ x, const float* __restrict__ rs) {
    __shared__ float tile[32][257];
    int b = blockIdx.x >> 8;
    int t0 = (blockIdx.x & 255) * 32;
    int w = threadIdx.x >> 5, lane = threadIdx.x & 31;
    #pragma unroll
    for (int rr = 0; rr < 4; rr++) {
        int tr = w * 4 + rr;
        size_t base = ((size_t)(b * LL + t0 + tr)) * DD;
        float v[8]; float ss = 0.f;
        #pragma unroll
        for (int k = 0; k < 8; k++) { v[k] = x[base + lane + 32 * k]; ss += v[k] * v[k]; }
        #pragma unroll
        for (int o = 16; o > 0; o >>= 1) ss += __shfl_xor_sync(0xffffffffu, ss, o);
        float inv = rsqrtf(ss * (1.f / DD) + 1e-6f);
        #pragma unroll
        for (int k = 0; k < 8; k++) tile[tr][lane + 32 * k] = v[k] * inv * rs[lane + 32 * k];
    }
    __syncthreads();
    #pragma unroll 8
    for (int dd = 0; dd < 32; dd++) {
        int d = w * 32 + dd;
        g_xt[((size_t)(b * DD + d)) * LL + t0 + lane] = tile[lane][d];
    }
}

// ---------------- kernel 2: 13-level dilated depthwise cascade + gelu -----------
__device__ __forceinline__ float gelu_f(float v) {
    float u = 0.7978845608028654f * (v + 0.044715f * v * v * v);
    return 0.5f * v * (1.f + tanhf(u));
}

__global__ void __launch_bounds__(256)
cascade_kernel(const float* __restrict__ h0,
               const float* __restrict__ h1,
               const float* __restrict__ wv) {
    extern __shared__ float sb[];
    float* srcb = sb;
    float* dstb = sb + LL;
    int b = blockIdx.x >> 8, d = blockIdx.x & 255;
    float h00 = h0[d * 2], h01 = h0[d * 2 + 1];
    float h10 = h1[d * 2], h11 = h1[d * 2 + 1];
    float w0 = wv[d];
    float wlast = wv[(NLEV + 1) * DD + d];
    size_t base = ((size_t)(b * DD + d)) * LL;
    int tid = threadIdx.x;
    float a[32], y[32];
    #pragma unroll
    for (int k = 0; k < 32; k++) {
        int t = tid + 256 * k;
        a[k] = g_xt[base + t];
        srcb[t] = a[k];
        y[k] = w0 * a[k];
    }
    for (int j = 0; j < 8; j++) {
        int dil = 1 << j;
        float wj = wv[(j + 1) * DD + d];
        __syncthreads();
        #pragma unroll
        for (int k = 0; k < 32; k++) {
            int t = tid + 256 * k;
            float prev = (t >= dil) ? srcb[t - dil] : 0.f;
            y[k] += wj * (h10 * prev + h11 * a[k]);
            a[k] = h00 * prev + h01 * a[k];
            if (j != 7) dstb[t] = a[k];
        }
        float* tmp = srcb; srcb = dstb; dstb = tmp;
    }
    #pragma unroll
    for (int j = 8; j < NLEV; j++) {
        int c = 1 << (j - 8);
        float wj = wv[(j + 1) * DD + d];
        #pragma unroll
        for (int k = 31; k >= 0; k--) {
            float prev = (k >= c) ? a[k - c] : 0.f;
            y[k] += wj * (h10 * prev + h11 * a[k]);
            a[k] = h00 * prev + h01 * a[k];
        }
    }
    #pragma unroll
    for (int k = 0; k < 32; k++) {
        int t = tid + 256 * k;
        g_yth[base + t] = __float2half_rn(gelu_f(y[k] + wlast * a[k]));
    }
}

// ---------------- kernel 2b: fp16 transpose (b,d,t) -> (b*L+t, d) ---------------
__global__ void __launch_bounds__(256)
transpose_h_kernel() {
    __shared__ uint32_t s2[32][65];   // [d-pair][t] half2(even d, odd d)
    int bid = blockIdx.x;             // 4 * 128 * 4 = 2048
    int b = bid >> 9;
    int rem = bid & 511;
    int t0 = (rem >> 2) * 64;
    int d0 = (rem & 3) * 64;
    int tid = threadIdx.x;
    {
        int dp = tid >> 3, ts = tid & 7;
        const __half* p0 = g_yth + ((size_t)(b * DD + d0 + 2 * dp)) * LL + t0 + ts * 8;
        uint4 e = *(const uint4*)p0;
        uint4 o = *(const uint4*)(p0 + LL);
        __half* eh = (__half*)&e; __half* oh = (__half*)&o;
        #pragma unroll
        for (int i = 0; i < 8; i++) {
            __half2 h = __halves2half2(eh[i], oh[i]);
            s2[dp][ts * 8 + i] = *(uint32_t*)&h;
        }
    }
    __syncthreads();
    {
        int t = tid >> 2, ds = tid & 3;
        uint32_t w[8];
        #pragma unroll
        for (int i = 0; i < 8; i++) w[i] = s2[ds * 8 + i][t];
        uint4* dst = (uint4*)(g_yh + ((size_t)(b * LL + t0 + t)) * DD + d0 + ds * 16);
        dst[0] = make_uint4(w[0], w[1], w[2], w[3]);
        dst[1] = make_uint4(w[4], w[5], w[6], w[7]);
    }
}

// ---------------- kernel 3: cp.async ldmatrix GEMM + GLU + residual -------------
__device__ __forceinline__ void mma16816(float* c, const uint32_t* a, const uint32_t* b) {
    asm("mma.sync.aligned.m16n8k16.row.col.f32.f16.f16.f32 "
        "{%0,%1,%2,%3}, {%4,%5,%6,%7}, {%8,%9}, {%0,%1,%2,%3};\n"
        : "+f"(c[0]), "+f"(c[1]), "+f"(c[2]), "+f"(c[3])
        : "r"(a[0]), "r"(a[1]), "r"(a[2]), "r"(a[3]), "r"(b[0]), "r"(b[1]));
}
__device__ __forceinline__ void ldsm4(uint32_t* r, uint32_t addr) {
    asm volatile("ldmatrix.sync.aligned.m8n8.x4.shared.b16 {%0,%1,%2,%3}, [%4];"
                 : "=r"(r[0]), "=r"(r[1]), "=r"(r[2]), "=r"(r[3]) : "r"(addr));
}
__device__ __forceinline__ uint32_t smem_u32(const void* p) {
    uint32_t a;
    asm("{ .reg .u64 t; cvta.to.shared.u64 t, %1; cvt.u32.u64 %0, t; }" : "=r"(a) : "l"(p));
    return a;
}
__device__ __forceinline__ void cpasync16(uint32_t dst, const void* src) {
    asm volatile("cp.async.cg.shared.global [%0], [%1], 16;" :: "r"(dst), "l"(src));
}

// smem layout (bytes):
//   B:      [n=128][pitch 132 words]         = 67584
//   A bufs: 2 x [m=128][k=64 fp16, pitch 144B] = 2*18432 = 36864
#define B_BYTES   67584
#define ACHUNK    18432
#define GEMM_SMEM (B_BYTES + 2 * ACHUNK)

__global__ void __launch_bounds__(512, 2)
gemm_glu_mma_kernel(const float* __restrict__ xin, float* __restrict__ out) {
    extern __shared__ char smem[];
    uint32_t sbase = smem_u32(smem);
    uint32_t b_smem = sbase;
    uint32_t a_smem = sbase + B_BYTES;

    int bid = blockIdx.x;               // 1024 = 256 m-tiles x 4 n-tiles
    int m0 = (bid >> 2) * 128;          // flat row (b*L + t)
    int n0 = (bid & 3) * 128;           // reordered column base

    int tid = threadIdx.x;
    int warp = tid >> 5, lane = tid & 31;
    int m0w = (warp >> 2) * 32, n0w = (warp & 3) * 32;
    int g = lane >> 2, tg = lane & 3;

    // ---- prologue: B whole-K preload + A chunk 0 via cp.async ----
    {
        int r = tid >> 2, seg = tid & 3;
        const uint4* src = (const uint4*)(g_whp + (size_t)(n0 + r) * 128 + seg * 32);
        uint32_t dst = b_smem + (uint32_t)(r * 132 + seg * 32) * 4;
        #pragma unroll
        for (int u = 0; u < 8; u++) cpasync16(dst + u * 16, src + u);
    }
    const __half* Agh = g_yh + (size_t)m0 * DD;
    {
        int r = tid >> 2, s = tid & 3;
        const char* src = (const char*)(Agh + (size_t)r * DD) + s * 16;
        uint32_t dst = a_smem + (uint32_t)(r * 144 + s * 16);
        cpasync16(dst, src);
        cpasync16(dst + 64, src + 64);
    }
    asm volatile("cp.async.commit_group;" ::: "memory");
    asm volatile("cp.async.wait_group 0;" ::: "memory");
    __syncthreads();

    // ldmatrix per-thread base offsets
    uint32_t aoff[2], boff[2];
    #pragma unroll
    for (int mi = 0; mi < 2; mi++)
        aoff[mi] = (uint32_t)((m0w + mi * 16 + (lane & 15)) * 144 + (lane >> 4) * 16);
    #pragma unroll
    for (int nj = 0; nj < 2; nj++)
        boff[nj] = b_smem + (uint32_t)((n0w + nj * 16 + ((lane >> 4) << 3) + (lane & 7)) * 132
                                       + ((lane >> 3) & 1) * 4) * 4;

    float acc[2][4][4];
    #pragma unroll
    for (int i = 0; i < 2; i++)
        #pragma unroll
        for (int j = 0; j < 4; j++)
            #pragma unroll
            for (int p = 0; p < 4; p++) acc[i][j][p] = 0.f;

    for (int kc = 0; kc < 4; kc++) {
        if (kc < 3) {
            int r = tid >> 2, s = tid & 3;
            const char* src = (const char*)(Agh + (size_t)r * DD + (kc + 1) * 64) + s * 16;
            uint32_t dst = a_smem + (uint32_t)(((kc + 1) & 1) * ACHUNK) + (uint32_t)(r * 144 + s * 16);
            cpasync16(dst, src);
            cpasync16(dst + 64, src + 64);
            asm volatile("cp.async.commit_group;" ::: "memory");
        }
        uint32_t abase = a_smem + (uint32_t)(kc & 1) * ACHUNK;
        #pragma unroll
        for (int ks = 0; ks < 4; ks++) {
            uint32_t ah[2][4], bf[2][4];
            ldsm4(ah[0], abase + aoff[0] + ks * 32);
            ldsm4(ah[1], abase + aoff[1] + ks * 32);
            ldsm4(bf[0], boff[0] + (uint32_t)(kc * 32 + ks * 8) * 4);
            ldsm4(bf[1], boff[1] + (uint32_t)(kc * 32 + ks * 8) * 4);
            // 8 mma, all distinct accumulators
            #pragma unroll
            for (int mi = 0; mi < 2; mi++)
                #pragma unroll
                for (int nj = 0; nj < 2; nj++) {
                    mma16816(acc[mi][nj * 2 + 0], ah[mi], &bf[nj][0]);
                    mma16816(acc[mi][nj * 2 + 1], ah[mi], &bf[nj][2]);
                }
        }
        if (kc < 3) {
            asm volatile("cp.async.wait_group 0;" ::: "memory");
            __syncthreads();
        }
    }

    // ---- epilogue: bias + GLU (paired cols) + residual, direct stores ----
    #pragma unroll
    for (int mi = 0; mi < 2; mi++) {
        int r0 = m0 + m0w + mi * 16 + g;
        #pragma unroll
        for (int ni = 0; ni < 4; ni++) {
            int np = n0 + n0w + ni * 8 + tg * 2;
            float bb0 = g_br[np], bb1 = g_br[np + 1];
            int oc = np >> 1;
            float s0 = acc[mi][ni][0] + bb0;
            float s1 = acc[mi][ni][1] + bb1;
            float s2 = acc[mi][ni][2] + bb0;
            float s3 = acc[mi][ni][3] + bb1;
            size_t o0 = (size_t)r0 * DD + oc;
            size_t o1 = (size_t)(r0 + 8) * DD + oc;
            out[o0] = s0 * (1.f / (1.f + __expf(-s1))) + xin[o0];
            out[o1] = s2 * (1.f / (1.f + __expf(-s3))) + xin[o1];
        }
    }
}

// ---------------- launch ---------------------------------------------------------
extern "C" void kernel_launch(void* const* d_in, const int* in_sizes, int n_in,
                              void* d_out, int out_size) {
    const float* x  = (const float*)d_in[0];  // (B, L, D)
    const float* rs = (const float*)d_in[1];  // (D,)
    const float* h0 = (const float*)d_in[2];  // (D, 2)
    const float* h1 = (const float*)d_in[3];  // (D, 2)
    const float* wv = (const float*)d_in[4];  // (15, D)
    const float* cw = (const float*)d_in[5];  // (D, 2D)
    const float* cb = (const float*)d_in[6];  // (2D,)
    float* out = (float*)d_out;

    cudaFuncSetAttribute(cascade_kernel, cudaFuncAttributeMaxDynamicSharedMemorySize, 2 * LL * 4);
    cudaFuncSetAttribute(gemm_glu_mma_kernel, cudaFuncAttributeMaxDynamicSharedMemorySize, GEMM_SMEM);

    prep_kernel<<<256, 256>>>(cw, cb);
    rmsnorm_kernel<<<BB * (LL / 32), 256>>>(x, rs);
    cascade_kernel<<<BB * DD, 256, 2 * LL * 4>>>(h0, h1, wv);
    transpose_h_kernel<<<BB * (LL / 64) * (DD / 64), 256>>>();
    gemm_glu_mma_kernel<<<BB * (LL / 128) * 4, 512, GEMM_SMEM>>>(x, out);
}